// round 1
// baseline (speedup 1.0000x reference)
#include <cuda_runtime.h>
#include <math.h>

// Problem constants (fixed-shape problem)
#define NN 100000
#define EEDGES 1600000
#define NEG_SLOPE 0.2f

// ---------------------------------------------------------------------------
// Scratch (device globals — allocation-free rule)
// ---------------------------------------------------------------------------
__device__ __align__(16) float g_feat[(size_t)NN * 128];   // projected features [N,H,D]
__device__ __align__(16) float g_el[(size_t)NN * 4];       // [N,H]
__device__ __align__(16) float g_er[(size_t)NN * 4];       // [N,H]
__device__ __align__(16) float g_ee[(size_t)EEDGES * 4];   // exp(edge logits) [E,H]
__device__ __align__(16) float g_denom[(size_t)NN * 4];    // softmax denominator [N,H]

// Vector atomic add (sm_90+)
__device__ __forceinline__ void red_add_v4(float* addr, float4 v) {
    asm volatile("red.global.add.v4.f32 [%0], {%1,%2,%3,%4};"
                 :: "l"(addr), "f"(v.x), "f"(v.y), "f"(v.z), "f"(v.w)
                 : "memory");
}

// ---------------------------------------------------------------------------
// Kernel 0: zero the softmax denominators
// ---------------------------------------------------------------------------
__global__ void zero_denom_kernel(int n) {
    int i = blockIdx.x * blockDim.x + threadIdx.x;
    if (i < n) g_denom[i] = 0.0f;
}

// ---------------------------------------------------------------------------
// Kernel 1: GEMM  g_feat = features @ W   (N x 128) @ (128 x 128)
// Block: 256 threads, computes 128 rows x 128 cols, 8x8 micro-tile per thread.
// A and W both staged in dynamic smem (128 KB).
// ---------------------------------------------------------------------------
__global__ void gemm_kernel(const float* __restrict__ A,
                            const float* __restrict__ W,
                            int N) {
    extern __shared__ float sm[];
    float* As = sm;               // [128][128]
    float* Ws = sm + 128 * 128;   // [128][128]

    int tid = threadIdx.x;
    int rowBase = blockIdx.x * 128;

    // Load W tile (full matrix), coalesced float4
    for (int i = tid; i < 128 * 32; i += 256) {
        ((float4*)Ws)[i] = ((const float4*)W)[i];
    }
    // Load A tile with row guard
    for (int i = tid; i < 128 * 32; i += 256) {
        int r = i >> 5;
        int gr = rowBase + r;
        float4 v = make_float4(0.f, 0.f, 0.f, 0.f);
        if (gr < N) v = ((const float4*)A)[(size_t)gr * 32 + (i & 31)];
        ((float4*)As)[i] = v;
    }
    __syncthreads();

    int tx = tid & 15;   // col group (8 cols)
    int ty = tid >> 4;   // row group (8 rows)

    float acc[8][8];
#pragma unroll
    for (int i = 0; i < 8; i++)
#pragma unroll
        for (int j = 0; j < 8; j++) acc[i][j] = 0.0f;

    const float* a0 = As + (ty * 8) * 128;

#pragma unroll 8
    for (int k = 0; k < 128; k++) {
        float a[8];
#pragma unroll
        for (int i = 0; i < 8; i++) a[i] = a0[i * 128 + k];
        float4 w0 = *(const float4*)(Ws + k * 128 + tx * 8);
        float4 w1 = *(const float4*)(Ws + k * 128 + tx * 8 + 4);
        float w[8] = {w0.x, w0.y, w0.z, w0.w, w1.x, w1.y, w1.z, w1.w};
#pragma unroll
        for (int i = 0; i < 8; i++)
#pragma unroll
            for (int j = 0; j < 8; j++)
                acc[i][j] = fmaf(a[i], w[j], acc[i][j]);
    }

#pragma unroll
    for (int i = 0; i < 8; i++) {
        int gr = rowBase + ty * 8 + i;
        if (gr < N) {
            float4 v0 = make_float4(acc[i][0], acc[i][1], acc[i][2], acc[i][3]);
            float4 v1 = make_float4(acc[i][4], acc[i][5], acc[i][6], acc[i][7]);
            ((float4*)g_feat)[(size_t)gr * 32 + tx * 2 + 0] = v0;
            ((float4*)g_feat)[(size_t)gr * 32 + tx * 2 + 1] = v1;
        }
    }
}

// ---------------------------------------------------------------------------
// Kernel 2: per-node attention logits el/er.  One warp per node.
// lane l owns cols [4l, 4l+4); head h = l/8; reduce over 8-lane groups.
// ---------------------------------------------------------------------------
__global__ void elr_kernel(const float* __restrict__ attn_l,
                           const float* __restrict__ attn_r,
                           int N) {
    int warp = (blockIdx.x * blockDim.x + threadIdx.x) >> 5;
    int lane = threadIdx.x & 31;
    if (warp >= N) return;

    float4 f  = ((const float4*)g_feat)[(size_t)warp * 32 + lane];
    float4 al = ((const float4*)attn_l)[lane];
    float4 ar = ((const float4*)attn_r)[lane];

    float pl = f.x * al.x + f.y * al.y + f.z * al.z + f.w * al.w;
    float pr = f.x * ar.x + f.y * ar.y + f.z * ar.z + f.w * ar.w;

#pragma unroll
    for (int s = 4; s >= 1; s >>= 1) {
        pl += __shfl_xor_sync(0xFFFFFFFFu, pl, s);
        pr += __shfl_xor_sync(0xFFFFFFFFu, pr, s);
    }
    if ((lane & 7) == 0) {
        int h = lane >> 3;
        g_el[warp * 4 + h] = pl;
        g_er[warp * 4 + h] = pr;
    }
}

// ---------------------------------------------------------------------------
// Kernel 3: edge logits -> exp -> denom accumulation.  One thread per edge.
// No segment-max: logits are O(+-5) so exp() is numerically safe; alpha is
// mathematically identical to the max-shifted softmax.
// ---------------------------------------------------------------------------
__global__ void edge_logits_kernel(const int* __restrict__ src,
                                   const int* __restrict__ dst,
                                   int E) {
    int e = blockIdx.x * blockDim.x + threadIdx.x;
    if (e >= E) return;
    int s = src[e];
    int d = dst[e];
    float4 a = ((const float4*)g_el)[s];
    float4 b = ((const float4*)g_er)[d];
    float4 v;
    v.x = a.x + b.x; v.y = a.y + b.y; v.z = a.z + b.z; v.w = a.w + b.w;
    v.x = v.x > 0.f ? v.x : NEG_SLOPE * v.x;
    v.y = v.y > 0.f ? v.y : NEG_SLOPE * v.y;
    v.z = v.z > 0.f ? v.z : NEG_SLOPE * v.z;
    v.w = v.w > 0.f ? v.w : NEG_SLOPE * v.w;
    v.x = __expf(v.x); v.y = __expf(v.y); v.z = __expf(v.z); v.w = __expf(v.w);
    ((float4*)g_ee)[e] = v;
    red_add_v4(g_denom + (size_t)d * 4, v);
}

// ---------------------------------------------------------------------------
// Kernel 4: weighted aggregation.  One warp per edge; lane l owns 4 floats.
//   out[dst, :] += alpha_h * feat[src, :]
// ---------------------------------------------------------------------------
__global__ void aggregate_kernel(const int* __restrict__ src,
                                 const int* __restrict__ dst,
                                 float* __restrict__ out,
                                 int E) {
    int warp = (blockIdx.x * blockDim.x + threadIdx.x) >> 5;
    int lane = threadIdx.x & 31;
    if (warp >= E) return;

    int s = src[warp];
    int d = dst[warp];
    int h = lane >> 3;

    float num = g_ee[(size_t)warp * 4 + h];
    float den = g_denom[(size_t)d * 4 + h];
    float alpha = __fdividef(num, fmaxf(den, 1e-9f));

    float4 f = ((const float4*)g_feat)[(size_t)s * 32 + lane];
    f.x *= alpha; f.y *= alpha; f.z *= alpha; f.w *= alpha;
    red_add_v4(out + (size_t)d * 128 + lane * 4, f);
}

// ---------------------------------------------------------------------------
// Kernel 5: bias + ELU (in place on out), float4 vectorized
// ---------------------------------------------------------------------------
__global__ void finalize_kernel(float* __restrict__ out,
                                const float* __restrict__ bias,
                                int total4) {
    int i = blockIdx.x * blockDim.x + threadIdx.x;
    if (i >= total4) return;
    float4 v = ((float4*)out)[i];
    float4 b = ((const float4*)bias)[i & 31];
    v.x += b.x; v.y += b.y; v.z += b.z; v.w += b.w;
    v.x = v.x > 0.f ? v.x : expm1f(v.x);
    v.y = v.y > 0.f ? v.y : expm1f(v.y);
    v.z = v.z > 0.f ? v.z : expm1f(v.z);
    v.w = v.w > 0.f ? v.w : expm1f(v.w);
    ((float4*)out)[i] = v;
}

// ---------------------------------------------------------------------------
// Launcher
// ---------------------------------------------------------------------------
extern "C" void kernel_launch(void* const* d_in, const int* in_sizes, int n_in,
                              void* d_out, int out_size) {
    const float* features = (const float*)d_in[0];
    const int*   src      = (const int*)d_in[1];
    const int*   dst      = (const int*)d_in[2];
    const float* W        = (const float*)d_in[3];
    const float* attn_l   = (const float*)d_in[4];
    const float* attn_r   = (const float*)d_in[5];
    const float* bias     = (const float*)d_in[6];
    float*       out      = (float*)d_out;

    int N = in_sizes[0] / 128;   // 100000
    int E = in_sizes[1];         // 1600000

    // zero accumulators (needed every graph replay)
    cudaMemsetAsync(d_out, 0, (size_t)out_size * sizeof(float));
    zero_denom_kernel<<<(N * 4 + 255) / 256, 256>>>(N * 4);

    // GEMM: 128 KB dynamic smem
    cudaFuncSetAttribute(gemm_kernel, cudaFuncAttributeMaxDynamicSharedMemorySize, 131072);
    gemm_kernel<<<(N + 127) / 128, 256, 131072>>>(features, W, N);

    // per-node logits: 8 warps / block
    elr_kernel<<<(N + 7) / 8, 256>>>(attn_l, attn_r, N);

    // edge logits + denom
    edge_logits_kernel<<<(E + 255) / 256, 256>>>(src, dst, E);

    // aggregation: 8 warps (edges) / block
    aggregate_kernel<<<(E + 7) / 8, 256>>>(src, dst, out, E);

    // bias + ELU
    int total4 = N * 32;
    finalize_kernel<<<(total4 + 255) / 256, 256>>>(out, bias, total4);
}

// round 3
// speedup vs baseline: 1.5332x; 1.5332x over previous
#include <cuda_runtime.h>
#include <math.h>

// Problem constants (fixed-shape problem)
#define NN 100000
#define EEDGES 1600000
#define NEG_SLOPE 0.2f
#define NBLK_SCAN ((NN + 1023) / 1024)   // 98

// ---------------------------------------------------------------------------
// Scratch (device globals — allocation-free rule)
// ---------------------------------------------------------------------------
__device__ __align__(16) float g_feat[(size_t)NN * 128];   // projected features [N,H,D]
__device__ __align__(16) float g_el[(size_t)NN * 4];       // [N,H]
__device__ __align__(16) float g_er[(size_t)NN * 4];       // [N,H]
__device__ __align__(16) float g_ees[(size_t)EEDGES * 4];  // exp(edge logits), dst-sorted
__device__ __align__(16) int   g_srcs[EEDGES];             // src id, dst-sorted
__device__ __align__(16) int   g_cnt[NN];                  // per-dst degree
__device__ __align__(16) int   g_cur[NN];                  // scatter cursor
__device__ __align__(16) int   g_off[NN];                  // block-local exclusive offsets
__device__ __align__(16) int   g_bsum[NBLK_SCAN + 32];     // per-scan-block totals
__device__ __align__(16) int   g_boff[NBLK_SCAN + 32];     // exclusive scan of block totals

// ---------------------------------------------------------------------------
// Kernel: zero counters
// ---------------------------------------------------------------------------
__global__ void zero_kernel(int n) {
    int i = blockIdx.x * blockDim.x + threadIdx.x;
    if (i < n) { g_cnt[i] = 0; g_cur[i] = 0; }
}

// ---------------------------------------------------------------------------
// Kernel: histogram of dst (2 edges per thread)
// ---------------------------------------------------------------------------
__global__ void hist_kernel(const int* __restrict__ dst, int E) {
    int e = (blockIdx.x * blockDim.x + threadIdx.x) * 2;
    if (e < E)     atomicAdd(&g_cnt[dst[e]], 1);
    if (e + 1 < E) atomicAdd(&g_cnt[dst[e + 1]], 1);
}

// ---------------------------------------------------------------------------
// Kernel: GEMM  g_feat = features @ W   (N x 128) @ (128 x 128)
// Block: 256 threads, 128x128 tile, 8x8 micro-tile per thread.
// ---------------------------------------------------------------------------
__global__ void gemm_kernel(const float* __restrict__ A,
                            const float* __restrict__ W,
                            int N) {
    extern __shared__ float sm[];
    float* As = sm;               // [128][128]
    float* Ws = sm + 128 * 128;   // [128][128]

    int tid = threadIdx.x;
    int rowBase = blockIdx.x * 128;

    for (int i = tid; i < 128 * 32; i += 256)
        ((float4*)Ws)[i] = ((const float4*)W)[i];
    for (int i = tid; i < 128 * 32; i += 256) {
        int r = i >> 5;
        int gr = rowBase + r;
        float4 v = make_float4(0.f, 0.f, 0.f, 0.f);
        if (gr < N) v = ((const float4*)A)[(size_t)gr * 32 + (i & 31)];
        ((float4*)As)[i] = v;
    }
    __syncthreads();

    int tx = tid & 15;
    int ty = tid >> 4;

    float acc[8][8];
#pragma unroll
    for (int i = 0; i < 8; i++)
#pragma unroll
        for (int j = 0; j < 8; j++) acc[i][j] = 0.0f;

    const float* a0 = As + (ty * 8) * 128;

#pragma unroll 8
    for (int k = 0; k < 128; k++) {
        float a[8];
#pragma unroll
        for (int i = 0; i < 8; i++) a[i] = a0[i * 128 + k];
        float4 w0 = *(const float4*)(Ws + k * 128 + tx * 8);
        float4 w1 = *(const float4*)(Ws + k * 128 + tx * 8 + 4);
        float w[8] = {w0.x, w0.y, w0.z, w0.w, w1.x, w1.y, w1.z, w1.w};
#pragma unroll
        for (int i = 0; i < 8; i++)
#pragma unroll
            for (int j = 0; j < 8; j++)
                acc[i][j] = fmaf(a[i], w[j], acc[i][j]);
    }

#pragma unroll
    for (int i = 0; i < 8; i++) {
        int gr = rowBase + ty * 8 + i;
        if (gr < N) {
            ((float4*)g_feat)[(size_t)gr * 32 + tx * 2 + 0] =
                make_float4(acc[i][0], acc[i][1], acc[i][2], acc[i][3]);
            ((float4*)g_feat)[(size_t)gr * 32 + tx * 2 + 1] =
                make_float4(acc[i][4], acc[i][5], acc[i][6], acc[i][7]);
        }
    }
}

// ---------------------------------------------------------------------------
// Kernel: per-node attention logits el/er. One warp per node.
// ---------------------------------------------------------------------------
__global__ void elr_kernel(const float* __restrict__ attn_l,
                           const float* __restrict__ attn_r,
                           int N) {
    int warp = (blockIdx.x * blockDim.x + threadIdx.x) >> 5;
    int lane = threadIdx.x & 31;
    if (warp >= N) return;

    float4 f  = ((const float4*)g_feat)[(size_t)warp * 32 + lane];
    float4 al = ((const float4*)attn_l)[lane];
    float4 ar = ((const float4*)attn_r)[lane];

    float pl = f.x * al.x + f.y * al.y + f.z * al.z + f.w * al.w;
    float pr = f.x * ar.x + f.y * ar.y + f.z * ar.z + f.w * ar.w;

#pragma unroll
    for (int s = 4; s >= 1; s >>= 1) {
        pl += __shfl_xor_sync(0xFFFFFFFFu, pl, s);
        pr += __shfl_xor_sync(0xFFFFFFFFu, pr, s);
    }
    if ((lane & 7) == 0) {
        int h = lane >> 3;
        g_el[warp * 4 + h] = pl;
        g_er[warp * 4 + h] = pr;
    }
}

// ---------------------------------------------------------------------------
// Scan A: per-1024-block exclusive scan of g_cnt -> g_off, totals -> g_bsum
// ---------------------------------------------------------------------------
__global__ void scanA_kernel(int N) {
    __shared__ int wtot[8];
    __shared__ int wexcl[8];
    int tid = threadIdx.x;
    int lane = tid & 31;
    int base = blockIdx.x * 1024 + tid * 4;

    int4 c = make_int4(0, 0, 0, 0);
    if (base + 3 < N) {
        c = *(const int4*)(g_cnt + base);
    } else {
        if (base + 0 < N) c.x = g_cnt[base + 0];
        if (base + 1 < N) c.y = g_cnt[base + 1];
        if (base + 2 < N) c.z = g_cnt[base + 2];
        if (base + 3 < N) c.w = g_cnt[base + 3];
    }
    int tsum = c.x + c.y + c.z + c.w;
    int incl = tsum;
#pragma unroll
    for (int s = 1; s < 32; s <<= 1) {
        int v = __shfl_up_sync(0xFFFFFFFFu, incl, s);
        if (lane >= s) incl += v;
    }
    if (lane == 31) wtot[tid >> 5] = incl;
    __syncthreads();
    if (tid == 0) {
        int r = 0;
#pragma unroll
        for (int w = 0; w < 8; w++) { wexcl[w] = r; r += wtot[w]; }
        g_bsum[blockIdx.x] = r;
    }
    __syncthreads();
    int p = wexcl[tid >> 5] + incl - tsum;
    if (base + 0 < N) g_off[base + 0] = p;
    if (base + 1 < N) g_off[base + 1] = p + c.x;
    if (base + 2 < N) g_off[base + 2] = p + c.x + c.y;
    if (base + 3 < N) g_off[base + 3] = p + c.x + c.y + c.z;
}

// ---------------------------------------------------------------------------
// Scan B: exclusive scan of block totals (single block, 128 threads)
// ---------------------------------------------------------------------------
__global__ void scanB_kernel(int nb) {
    __shared__ int wtot[4];
    __shared__ int wexcl[4];
    int t = threadIdx.x;
    int lane = t & 31;
    int v = (t < nb) ? g_bsum[t] : 0;
    int incl = v;
#pragma unroll
    for (int s = 1; s < 32; s <<= 1) {
        int u = __shfl_up_sync(0xFFFFFFFFu, incl, s);
        if (lane >= s) incl += u;
    }
    if (lane == 31) wtot[t >> 5] = incl;
    __syncthreads();
    if (t == 0) {
        int r = 0;
#pragma unroll
        for (int w = 0; w < 4; w++) { wexcl[w] = r; r += wtot[w]; }
    }
    __syncthreads();
    if (t < nb) g_boff[t] = wexcl[t >> 5] + incl - v;
}

// ---------------------------------------------------------------------------
// Kernel: edge logits -> exp -> scatter into dst-sorted arrays
// ---------------------------------------------------------------------------
__global__ void edge_scatter_kernel(const int* __restrict__ src,
                                    const int* __restrict__ dst,
                                    int E) {
    int e = blockIdx.x * blockDim.x + threadIdx.x;
    if (e >= E) return;
    int s = src[e];
    int d = dst[e];
    float4 a = ((const float4*)g_el)[s];
    float4 b = ((const float4*)g_er)[d];
    float4 v;
    v.x = a.x + b.x; v.y = a.y + b.y; v.z = a.z + b.z; v.w = a.w + b.w;
    v.x = v.x > 0.f ? v.x : NEG_SLOPE * v.x;
    v.y = v.y > 0.f ? v.y : NEG_SLOPE * v.y;
    v.z = v.z > 0.f ? v.z : NEG_SLOPE * v.z;
    v.w = v.w > 0.f ? v.w : NEG_SLOPE * v.w;
    v.x = __expf(v.x); v.y = __expf(v.y); v.z = __expf(v.z); v.w = __expf(v.w);

    int r = atomicAdd(&g_cur[d], 1);
    int pos = __ldg(&g_off[d]) + __ldg(&g_boff[d >> 10]) + r;
    g_srcs[pos] = s;
    ((float4*)g_ees)[pos] = v;
}

// ---------------------------------------------------------------------------
// Kernel: gather aggregation. One warp per dst node. No output atomics.
// Fuses softmax normalization + bias + ELU.
// ---------------------------------------------------------------------------
__global__ void __launch_bounds__(256)
aggregate_kernel(const float* __restrict__ bias,
                 float* __restrict__ out,
                 int N) {
    int node = (blockIdx.x * blockDim.x + threadIdx.x) >> 5;
    int lane = threadIdx.x & 31;
    if (node >= N) return;

    int off = g_off[node] + g_boff[node >> 10];
    int cnt = g_cnt[node];
    int h = lane >> 3;

    float4 acc = make_float4(0.f, 0.f, 0.f, 0.f);
    float den = 0.f;

    const float4* feat4 = (const float4*)g_feat;

    int i = 0;
    for (; i + 2 <= cnt; i += 2) {
        int p0 = off + i, p1 = off + i + 1;
        int s0 = g_srcs[p0];
        int s1 = g_srcs[p1];
        float w0 = g_ees[(size_t)p0 * 4 + h];
        float w1 = g_ees[(size_t)p1 * 4 + h];
        float4 f0 = feat4[(size_t)s0 * 32 + lane];
        float4 f1 = feat4[(size_t)s1 * 32 + lane];
        den += w0 + w1;
        acc.x = fmaf(w0, f0.x, acc.x);
        acc.y = fmaf(w0, f0.y, acc.y);
        acc.z = fmaf(w0, f0.z, acc.z);
        acc.w = fmaf(w0, f0.w, acc.w);
        acc.x = fmaf(w1, f1.x, acc.x);
        acc.y = fmaf(w1, f1.y, acc.y);
        acc.z = fmaf(w1, f1.z, acc.z);
        acc.w = fmaf(w1, f1.w, acc.w);
    }
    if (i < cnt) {
        int p0 = off + i;
        int s0 = g_srcs[p0];
        float w0 = g_ees[(size_t)p0 * 4 + h];
        float4 f0 = feat4[(size_t)s0 * 32 + lane];
        den += w0;
        acc.x = fmaf(w0, f0.x, acc.x);
        acc.y = fmaf(w0, f0.y, acc.y);
        acc.z = fmaf(w0, f0.z, acc.z);
        acc.w = fmaf(w0, f0.w, acc.w);
    }

    float inv = __fdividef(1.0f, fmaxf(den, 1e-9f));
    float4 bvec = ((const float4*)bias)[lane];
    acc.x = acc.x * inv + bvec.x;
    acc.y = acc.y * inv + bvec.y;
    acc.z = acc.z * inv + bvec.z;
    acc.w = acc.w * inv + bvec.w;
    acc.x = acc.x > 0.f ? acc.x : expm1f(acc.x);
    acc.y = acc.y > 0.f ? acc.y : expm1f(acc.y);
    acc.z = acc.z > 0.f ? acc.z : expm1f(acc.z);
    acc.w = acc.w > 0.f ? acc.w : expm1f(acc.w);
    ((float4*)out)[(size_t)node * 32 + lane] = acc;
}

// ---------------------------------------------------------------------------
// Launcher
// ---------------------------------------------------------------------------
extern "C" void kernel_launch(void* const* d_in, const int* in_sizes, int n_in,
                              void* d_out, int out_size) {
    const float* features = (const float*)d_in[0];
    const int*   src      = (const int*)d_in[1];
    const int*   dst      = (const int*)d_in[2];
    const float* W        = (const float*)d_in[3];
    const float* attn_l   = (const float*)d_in[4];
    const float* attn_r   = (const float*)d_in[5];
    const float* bias     = (const float*)d_in[6];
    float*       out      = (float*)d_out;

    int N = in_sizes[0] / 128;   // 100000
    int E = in_sizes[1];         // 1600000
    int nb = (N + 1023) / 1024;  // scan blocks

    // zero counters
    zero_kernel<<<(N + 255) / 256, 256>>>(N);

    // dst histogram (2 edges/thread)
    hist_kernel<<<(E / 2 + 255) / 256, 256>>>(dst, E);

    // GEMM: 128 KB dynamic smem
    cudaFuncSetAttribute(gemm_kernel, cudaFuncAttributeMaxDynamicSharedMemorySize, 131072);
    gemm_kernel<<<(N + 127) / 128, 256, 131072>>>(features, W, N);

    // per-node logits
    elr_kernel<<<(N + 7) / 8, 256>>>(attn_l, attn_r, N);

    // offsets: two-level exclusive scan
    scanA_kernel<<<nb, 256>>>(N);
    scanB_kernel<<<1, 128>>>(nb);

    // edge logits + scatter into dst-sorted order
    edge_scatter_kernel<<<(E + 255) / 256, 256>>>(src, dst, E);

    // gather aggregation + bias + ELU (one warp per node)
    aggregate_kernel<<<(N + 7) / 8, 256>>>(bias, out, N);
}

// round 4
// speedup vs baseline: 1.8028x; 1.1759x over previous
#include <cuda_runtime.h>
#include <math.h>

// Problem constants (fixed-shape problem)
#define NN 100000
#define EEDGES 1600000
#define NEG_SLOPE 0.2f
#define NBLK_SCAN ((NN + 1023) / 1024)   // 98

// ---------------------------------------------------------------------------
// Scratch (device globals — allocation-free rule)
// ---------------------------------------------------------------------------
__device__ __align__(16) float g_feat[(size_t)NN * 128];   // projected features [N,H,D]
__device__ __align__(16) float g_el[(size_t)NN * 4];       // [N,H]
__device__ __align__(16) float g_er[(size_t)NN * 4];       // [N,H]
__device__ __align__(16) int   g_srcs[EEDGES];             // src id, dst-sorted
__device__ __align__(16) int   g_cnt[NN];                  // per-dst degree
__device__ __align__(16) int   g_cur[NN];                  // scatter cursor
__device__ __align__(16) int   g_off[NN];                  // block-local exclusive offsets
__device__ __align__(16) int   g_bsum[NBLK_SCAN + 32];     // per-scan-block totals
__device__ __align__(16) int   g_boff[NBLK_SCAN + 32];     // exclusive scan of block totals

// ---------------------------------------------------------------------------
// Kernel: zero counters
// ---------------------------------------------------------------------------
__global__ void zero_kernel(int n) {
    int i = blockIdx.x * blockDim.x + threadIdx.x;
    if (i < n) { g_cnt[i] = 0; g_cur[i] = 0; }
}

// ---------------------------------------------------------------------------
// Kernel: histogram of dst (2 edges per thread)
// ---------------------------------------------------------------------------
__global__ void hist_kernel(const int* __restrict__ dst, int E) {
    int e = (blockIdx.x * blockDim.x + threadIdx.x) * 2;
    if (e < E)     atomicAdd(&g_cnt[dst[e]], 1);
    if (e + 1 < E) atomicAdd(&g_cnt[dst[e + 1]], 1);
}

// ---------------------------------------------------------------------------
// Kernel: GEMM  g_feat = features @ W  (N x 128)(128 x 128), fused el/er.
// Block: 256 threads, 128x128 tile, 8x8 micro-tile per thread.
// Epilogue: el[n,h] = feat[n,h,:]·attn_l[h,:], er likewise, straight from acc.
// ---------------------------------------------------------------------------
__global__ void gemm_kernel(const float* __restrict__ A,
                            const float* __restrict__ W,
                            const float* __restrict__ attn_l,
                            const float* __restrict__ attn_r,
                            int N) {
    extern __shared__ float sm[];
    float* As = sm;               // [128][128]
    float* Ws = sm + 128 * 128;   // [128][128]

    int tid = threadIdx.x;
    int rowBase = blockIdx.x * 128;

    for (int i = tid; i < 128 * 32; i += 256)
        ((float4*)Ws)[i] = ((const float4*)W)[i];
    for (int i = tid; i < 128 * 32; i += 256) {
        int r = i >> 5;
        int gr = rowBase + r;
        float4 v = make_float4(0.f, 0.f, 0.f, 0.f);
        if (gr < N) v = ((const float4*)A)[(size_t)gr * 32 + (i & 31)];
        ((float4*)As)[i] = v;
    }
    __syncthreads();

    int tx = tid & 15;   // col block of 8 (head = tx>>2)
    int ty = tid >> 4;   // row block of 8

    float acc[8][8];
#pragma unroll
    for (int i = 0; i < 8; i++)
#pragma unroll
        for (int j = 0; j < 8; j++) acc[i][j] = 0.0f;

    const float* a0 = As + (ty * 8) * 128;

#pragma unroll 8
    for (int k = 0; k < 128; k++) {
        float a[8];
#pragma unroll
        for (int i = 0; i < 8; i++) a[i] = a0[i * 128 + k];
        float4 w0 = *(const float4*)(Ws + k * 128 + tx * 8);
        float4 w1 = *(const float4*)(Ws + k * 128 + tx * 8 + 4);
        float w[8] = {w0.x, w0.y, w0.z, w0.w, w1.x, w1.y, w1.z, w1.w};
#pragma unroll
        for (int i = 0; i < 8; i++)
#pragma unroll
            for (int j = 0; j < 8; j++)
                acc[i][j] = fmaf(a[i], w[j], acc[i][j]);
    }

    // write projected features
#pragma unroll
    for (int i = 0; i < 8; i++) {
        int gr = rowBase + ty * 8 + i;
        if (gr < N) {
            ((float4*)g_feat)[(size_t)gr * 32 + tx * 2 + 0] =
                make_float4(acc[i][0], acc[i][1], acc[i][2], acc[i][3]);
            ((float4*)g_feat)[(size_t)gr * 32 + tx * 2 + 1] =
                make_float4(acc[i][4], acc[i][5], acc[i][6], acc[i][7]);
        }
    }

    // fused el/er epilogue
    float al8[8], ar8[8];
#pragma unroll
    for (int j = 0; j < 8; j++) {
        al8[j] = __ldg(&attn_l[tx * 8 + j]);
        ar8[j] = __ldg(&attn_r[tx * 8 + j]);
    }
#pragma unroll
    for (int i = 0; i < 8; i++) {
        float pl = 0.f, pr = 0.f;
#pragma unroll
        for (int j = 0; j < 8; j++) {
            pl = fmaf(acc[i][j], al8[j], pl);
            pr = fmaf(acc[i][j], ar8[j], pr);
        }
        // reduce over the 4 tx-threads of this head (adjacent lanes)
        pl += __shfl_xor_sync(0xFFFFFFFFu, pl, 1);
        pl += __shfl_xor_sync(0xFFFFFFFFu, pl, 2);
        pr += __shfl_xor_sync(0xFFFFFFFFu, pr, 1);
        pr += __shfl_xor_sync(0xFFFFFFFFu, pr, 2);
        int gr = rowBase + ty * 8 + i;
        if ((tx & 3) == 0 && gr < N) {
            int h = tx >> 2;
            g_el[gr * 4 + h] = pl;
            g_er[gr * 4 + h] = pr;
        }
    }
}

// ---------------------------------------------------------------------------
// Scan A: per-1024-block exclusive scan of g_cnt -> g_off, totals -> g_bsum
// ---------------------------------------------------------------------------
__global__ void scanA_kernel(int N) {
    __shared__ int wtot[8];
    __shared__ int wexcl[8];
    int tid = threadIdx.x;
    int lane = tid & 31;
    int base = blockIdx.x * 1024 + tid * 4;

    int4 c = make_int4(0, 0, 0, 0);
    if (base + 3 < N) {
        c = *(const int4*)(g_cnt + base);
    } else {
        if (base + 0 < N) c.x = g_cnt[base + 0];
        if (base + 1 < N) c.y = g_cnt[base + 1];
        if (base + 2 < N) c.z = g_cnt[base + 2];
        if (base + 3 < N) c.w = g_cnt[base + 3];
    }
    int tsum = c.x + c.y + c.z + c.w;
    int incl = tsum;
#pragma unroll
    for (int s = 1; s < 32; s <<= 1) {
        int v = __shfl_up_sync(0xFFFFFFFFu, incl, s);
        if (lane >= s) incl += v;
    }
    if (lane == 31) wtot[tid >> 5] = incl;
    __syncthreads();
    if (tid == 0) {
        int r = 0;
#pragma unroll
        for (int w = 0; w < 8; w++) { wexcl[w] = r; r += wtot[w]; }
        g_bsum[blockIdx.x] = r;
    }
    __syncthreads();
    int p = wexcl[tid >> 5] + incl - tsum;
    if (base + 0 < N) g_off[base + 0] = p;
    if (base + 1 < N) g_off[base + 1] = p + c.x;
    if (base + 2 < N) g_off[base + 2] = p + c.x + c.y;
    if (base + 3 < N) g_off[base + 3] = p + c.x + c.y + c.z;
}

// ---------------------------------------------------------------------------
// Scan B: exclusive scan of block totals (single block, 128 threads)
// ---------------------------------------------------------------------------
__global__ void scanB_kernel(int nb) {
    __shared__ int wtot[4];
    __shared__ int wexcl[4];
    int t = threadIdx.x;
    int lane = t & 31;
    int v = (t < nb) ? g_bsum[t] : 0;
    int incl = v;
#pragma unroll
    for (int s = 1; s < 32; s <<= 1) {
        int u = __shfl_up_sync(0xFFFFFFFFu, incl, s);
        if (lane >= s) incl += u;
    }
    if (lane == 31) wtot[t >> 5] = incl;
    __syncthreads();
    if (t == 0) {
        int r = 0;
#pragma unroll
        for (int w = 0; w < 4; w++) { wexcl[w] = r; r += wtot[w]; }
    }
    __syncthreads();
    if (t < nb) g_boff[t] = wexcl[t >> 5] + incl - v;
}

// ---------------------------------------------------------------------------
// Kernel: permute src ids into dst-sorted order (no logits here anymore)
// ---------------------------------------------------------------------------
__global__ void edge_scatter_kernel(const int* __restrict__ src,
                                    const int* __restrict__ dst,
                                    int E) {
    int e = blockIdx.x * blockDim.x + threadIdx.x;
    if (e >= E) return;
    int s = src[e];
    int d = dst[e];
    int r = atomicAdd(&g_cur[d], 1);
    int pos = __ldg(&g_off[d]) + __ldg(&g_boff[d >> 10]) + r;
    g_srcs[pos] = s;
}

// ---------------------------------------------------------------------------
// Kernel: gather aggregation. One warp per dst node. Computes logits, exp,
// softmax, weighted feature sum, bias + ELU; streaming store of output.
// ---------------------------------------------------------------------------
__global__ void __launch_bounds__(256)
aggregate_kernel(const float* __restrict__ bias,
                 float* __restrict__ out,
                 int N) {
    int node = (blockIdx.x * blockDim.x + threadIdx.x) >> 5;
    int lane = threadIdx.x & 31;
    if (node >= N) return;

    int off = g_off[node] + g_boff[node >> 10];
    int cnt = g_cnt[node];
    int h = lane >> 3;

    float er_h = g_er[node * 4 + h];

    float4 acc = make_float4(0.f, 0.f, 0.f, 0.f);
    float den = 0.f;

    const float4* feat4 = (const float4*)g_feat;

    int i = 0;
    for (; i + 4 <= cnt; i += 4) {
        int s0 = g_srcs[off + i + 0];
        int s1 = g_srcs[off + i + 1];
        int s2 = g_srcs[off + i + 2];
        int s3 = g_srcs[off + i + 3];
        float e0 = __ldg(&g_el[s0 * 4 + h]) + er_h;
        float e1 = __ldg(&g_el[s1 * 4 + h]) + er_h;
        float e2 = __ldg(&g_el[s2 * 4 + h]) + er_h;
        float e3 = __ldg(&g_el[s3 * 4 + h]) + er_h;
        float4 f0 = feat4[(size_t)s0 * 32 + lane];
        float4 f1 = feat4[(size_t)s1 * 32 + lane];
        float4 f2 = feat4[(size_t)s2 * 32 + lane];
        float4 f3 = feat4[(size_t)s3 * 32 + lane];
        e0 = e0 > 0.f ? e0 : NEG_SLOPE * e0;
        e1 = e1 > 0.f ? e1 : NEG_SLOPE * e1;
        e2 = e2 > 0.f ? e2 : NEG_SLOPE * e2;
        e3 = e3 > 0.f ? e3 : NEG_SLOPE * e3;
        float w0 = __expf(e0), w1 = __expf(e1), w2 = __expf(e2), w3 = __expf(e3);
        den += (w0 + w1) + (w2 + w3);
        acc.x = fmaf(w0, f0.x, acc.x); acc.y = fmaf(w0, f0.y, acc.y);
        acc.z = fmaf(w0, f0.z, acc.z); acc.w = fmaf(w0, f0.w, acc.w);
        acc.x = fmaf(w1, f1.x, acc.x); acc.y = fmaf(w1, f1.y, acc.y);
        acc.z = fmaf(w1, f1.z, acc.z); acc.w = fmaf(w1, f1.w, acc.w);
        acc.x = fmaf(w2, f2.x, acc.x); acc.y = fmaf(w2, f2.y, acc.y);
        acc.z = fmaf(w2, f2.z, acc.z); acc.w = fmaf(w2, f2.w, acc.w);
        acc.x = fmaf(w3, f3.x, acc.x); acc.y = fmaf(w3, f3.y, acc.y);
        acc.z = fmaf(w3, f3.z, acc.z); acc.w = fmaf(w3, f3.w, acc.w);
    }
    for (; i < cnt; i++) {
        int s0 = g_srcs[off + i];
        float e0 = __ldg(&g_el[s0 * 4 + h]) + er_h;
        e0 = e0 > 0.f ? e0 : NEG_SLOPE * e0;
        float w0 = __expf(e0);
        float4 f0 = feat4[(size_t)s0 * 32 + lane];
        den += w0;
        acc.x = fmaf(w0, f0.x, acc.x); acc.y = fmaf(w0, f0.y, acc.y);
        acc.z = fmaf(w0, f0.z, acc.z); acc.w = fmaf(w0, f0.w, acc.w);
    }

    float inv = __fdividef(1.0f, fmaxf(den, 1e-9f));
    float4 bvec = ((const float4*)bias)[lane];
    acc.x = acc.x * inv + bvec.x;
    acc.y = acc.y * inv + bvec.y;
    acc.z = acc.z * inv + bvec.z;
    acc.w = acc.w * inv + bvec.w;
    acc.x = acc.x > 0.f ? acc.x : expm1f(acc.x);
    acc.y = acc.y > 0.f ? acc.y : expm1f(acc.y);
    acc.z = acc.z > 0.f ? acc.z : expm1f(acc.z);
    acc.w = acc.w > 0.f ? acc.w : expm1f(acc.w);
    __stcs(&((float4*)out)[(size_t)node * 32 + lane], acc);
}

// ---------------------------------------------------------------------------
// Launcher — sort chain forked onto a side stream, overlapping the GEMM.
// ---------------------------------------------------------------------------
extern "C" void kernel_launch(void* const* d_in, const int* in_sizes, int n_in,
                              void* d_out, int out_size) {
    const float* features = (const float*)d_in[0];
    const int*   src      = (const int*)d_in[1];
    const int*   dst      = (const int*)d_in[2];
    const float* W        = (const float*)d_in[3];
    const float* attn_l   = (const float*)d_in[4];
    const float* attn_r   = (const float*)d_in[5];
    const float* bias     = (const float*)d_in[6];
    float*       out      = (float*)d_out;

    int N = in_sizes[0] / 128;   // 100000
    int E = in_sizes[1];         // 1600000
    int nb = (N + 1023) / 1024;  // scan blocks

    cudaStream_t s2;
    cudaStreamCreateWithFlags(&s2, cudaStreamNonBlocking);
    cudaEvent_t evFork, evJoin;
    cudaEventCreateWithFlags(&evFork, cudaEventDisableTiming);
    cudaEventCreateWithFlags(&evJoin, cudaEventDisableTiming);

    // fork side stream from the (capture) default stream
    cudaEventRecord(evFork, 0);
    cudaStreamWaitEvent(s2, evFork, 0);

    // side stream: counting-sort chain (independent of GEMM)
    zero_kernel<<<(N + 255) / 256, 256, 0, s2>>>(N);
    hist_kernel<<<(E / 2 + 255) / 256, 256, 0, s2>>>(dst, E);
    scanA_kernel<<<nb, 256, 0, s2>>>(N);
    scanB_kernel<<<1, 128, 0, s2>>>(nb);
    edge_scatter_kernel<<<(E + 255) / 256, 256, 0, s2>>>(src, dst, E);
    cudaEventRecord(evJoin, s2);

    // default stream: GEMM with fused el/er epilogue
    cudaFuncSetAttribute(gemm_kernel, cudaFuncAttributeMaxDynamicSharedMemorySize, 131072);
    gemm_kernel<<<(N + 127) / 128, 256, 131072>>>(features, W, attn_l, attn_r, N);

    // join, then aggregate
    cudaStreamWaitEvent(0, evJoin, 0);
    aggregate_kernel<<<(N + 7) / 8, 256>>>(bias, out, N);
}

// round 6
// speedup vs baseline: 1.8952x; 1.0512x over previous
#include <cuda_runtime.h>
#include <math.h>
#include <stdint.h>

// Problem constants (fixed-shape problem)
#define NN 100000
#define EEDGES 1600000
#define NEG_SLOPE 0.2f
#define NBLK_SCAN ((NN + 1023) / 1024)   // 98

// Padded smem strides (floats) for conflict-free mma fragment loads
#define AS_STRIDE 132   // mod 32 = 4  -> A-frag banks 4*r + (k+c), all distinct
#define WS_STRIDE 136   // mod 32 = 8  -> B-frag banks 8*k + n, all distinct

// ---------------------------------------------------------------------------
// Scratch (device globals — allocation-free rule)
// ---------------------------------------------------------------------------
__device__ __align__(16) float g_feat[(size_t)NN * 128];   // projected features [N,H,D]
__device__ __align__(16) float g_el[(size_t)NN * 4];       // [N,H]
__device__ __align__(16) float g_er[(size_t)NN * 4];       // [N,H]
__device__ __align__(16) int   g_srcs[EEDGES];             // src id, dst-sorted
__device__ __align__(16) int   g_cnt[NN];                  // per-dst degree
__device__ __align__(16) int   g_cur[NN];                  // scatter cursor
__device__ __align__(16) int   g_off[NN];                  // block-local exclusive offsets
__device__ __align__(16) int   g_bsum[NBLK_SCAN + 32];     // per-scan-block totals
__device__ __align__(16) int   g_boff[NBLK_SCAN + 32];     // exclusive scan of block totals

// ---------------------------------------------------------------------------
// tf32 helpers
// ---------------------------------------------------------------------------
__device__ __forceinline__ uint32_t f2tf32(float x) {
    uint32_t r;
    asm("cvt.rna.tf32.f32 %0, %1;" : "=r"(r) : "f"(x));
    return r;
}
__device__ __forceinline__ void split_tf32(float x, uint32_t& hi, uint32_t& lo) {
    hi = f2tf32(x);
    lo = f2tf32(x - __uint_as_float(hi));
}
__device__ __forceinline__ void mma_tf32(float c[4],
                                         uint32_t a0, uint32_t a1, uint32_t a2, uint32_t a3,
                                         uint32_t b0, uint32_t b1) {
    asm("mma.sync.aligned.m16n8k8.row.col.f32.tf32.tf32.f32 "
        "{%0,%1,%2,%3},{%4,%5,%6,%7},{%8,%9},{%0,%1,%2,%3};"
        : "+f"(c[0]), "+f"(c[1]), "+f"(c[2]), "+f"(c[3])
        : "r"(a0), "r"(a1), "r"(a2), "r"(a3), "r"(b0), "r"(b1));
}

// ---------------------------------------------------------------------------
// Kernel: zero counters
// ---------------------------------------------------------------------------
__global__ void zero_kernel(int n) {
    int i = blockIdx.x * blockDim.x + threadIdx.x;
    if (i < n) { g_cnt[i] = 0; g_cur[i] = 0; }
}

// ---------------------------------------------------------------------------
// Kernel: histogram of dst (2 edges per thread)
// ---------------------------------------------------------------------------
__global__ void hist_kernel(const int* __restrict__ dst, int E) {
    int e = (blockIdx.x * blockDim.x + threadIdx.x) * 2;
    if (e < E)     atomicAdd(&g_cnt[dst[e]], 1);
    if (e + 1 < E) atomicAdd(&g_cnt[dst[e + 1]], 1);
}

// ---------------------------------------------------------------------------
// Kernel: GEMM via tensor cores (3xTF32), fused el/er epilogue.
// Block: 256 threads (8 warps), tile 128(M) x 128(N), K=128.
// Warp tile: 32(M) x 64(N).  warpM = wid>>1, warpN = wid&1.
// Each head (32 cols) lives wholly inside one warp -> el/er via shfl only.
// ---------------------------------------------------------------------------
__global__ void __launch_bounds__(256, 1)
gemm_kernel(const float* __restrict__ A,
            const float* __restrict__ W,
            const float* __restrict__ attn_l,
            const float* __restrict__ attn_r,
            int N) {
    extern __shared__ float sm[];
    float* As = sm;                       // [128][AS_STRIDE]
    float* Ws = sm + 128 * AS_STRIDE;     // [128][WS_STRIDE]  (Ws[k][n])

    int tid = threadIdx.x;
    int rowBase = blockIdx.x * 128;

    // Load W (k-major 128x128) into padded smem
    for (int i = tid; i < 128 * 32; i += 256) {
        int k = i >> 5, c4 = i & 31;
        float4 v = ((const float4*)W)[(size_t)k * 32 + c4];
        *(float4*)(Ws + k * WS_STRIDE + c4 * 4) = v;
    }
    // Load A tile into padded smem (guarded)
    for (int i = tid; i < 128 * 32; i += 256) {
        int r = i >> 5, c4 = i & 31;
        int gr = rowBase + r;
        float4 v = make_float4(0.f, 0.f, 0.f, 0.f);
        if (gr < N) v = ((const float4*)A)[(size_t)gr * 32 + c4];
        *(float4*)(As + r * AS_STRIDE + c4 * 4) = v;
    }
    __syncthreads();

    int wid  = tid >> 5;
    int lane = tid & 31;
    int grp  = lane >> 2;    // 0..7
    int tig  = lane & 3;     // 0..3
    int warpM = wid >> 1;    // 0..3
    int warpN = wid & 1;     // 0..1

    float C[2][8][4];
#pragma unroll
    for (int mt = 0; mt < 2; mt++)
#pragma unroll
        for (int nt = 0; nt < 8; nt++)
#pragma unroll
            for (int q = 0; q < 4; q++) C[mt][nt][q] = 0.f;

#pragma unroll 2
    for (int step = 0; step < 16; step++) {
        int k0 = step * 8;

        // A fragments: row = mbase+grp (and +8), col = k0 + tig (and +4)
        uint32_t Ah[2][4], Al[2][4];
#pragma unroll
        for (int mt = 0; mt < 2; mt++) {
            int mbase = warpM * 32 + mt * 16;
            const float* ap = As + (mbase + grp) * AS_STRIDE + k0 + tig;
            float a0 = ap[0];
            float a1 = ap[8 * AS_STRIDE];
            float a2 = ap[4];
            float a3 = ap[8 * AS_STRIDE + 4];
            split_tf32(a0, Ah[mt][0], Al[mt][0]);
            split_tf32(a1, Ah[mt][1], Al[mt][1]);
            split_tf32(a2, Ah[mt][2], Al[mt][2]);
            split_tf32(a3, Ah[mt][3], Al[mt][3]);
        }

        // B fragments: k = k0 + tig (and +4), n = nbase + grp
        uint32_t Bh[8][2], Bl[8][2];
#pragma unroll
        for (int nt = 0; nt < 8; nt++) {
            int nbase = warpN * 64 + nt * 8;
            const float* bp = Ws + (k0 + tig) * WS_STRIDE + nbase + grp;
            float b0 = bp[0];
            float b1 = bp[4 * WS_STRIDE];
            split_tf32(b0, Bh[nt][0], Bl[nt][0]);
            split_tf32(b1, Bh[nt][1], Bl[nt][1]);
        }

#pragma unroll
        for (int mt = 0; mt < 2; mt++)
#pragma unroll
            for (int nt = 0; nt < 8; nt++) {
                mma_tf32(C[mt][nt], Ah[mt][0], Ah[mt][1], Ah[mt][2], Ah[mt][3],
                         Bh[nt][0], Bh[nt][1]);
                mma_tf32(C[mt][nt], Al[mt][0], Al[mt][1], Al[mt][2], Al[mt][3],
                         Bh[nt][0], Bh[nt][1]);
                mma_tf32(C[mt][nt], Ah[mt][0], Ah[mt][1], Ah[mt][2], Ah[mt][3],
                         Bl[nt][0], Bl[nt][1]);
            }
    }

    // ---- store feat ----
#pragma unroll
    for (int mt = 0; mt < 2; mt++) {
        int row0 = rowBase + warpM * 32 + mt * 16 + grp;
#pragma unroll
        for (int nt = 0; nt < 8; nt++) {
            int col = warpN * 64 + nt * 8 + 2 * tig;
            if (row0 < N)
                *(float2*)&g_feat[(size_t)row0 * 128 + col] =
                    make_float2(C[mt][nt][0], C[mt][nt][1]);
            if (row0 + 8 < N)
                *(float2*)&g_feat[(size_t)(row0 + 8) * 128 + col] =
                    make_float2(C[mt][nt][2], C[mt][nt][3]);
        }
    }

    // ---- fused el/er epilogue ----
    float alv[8][2], arv[8][2];
#pragma unroll
    for (int nt = 0; nt < 8; nt++) {
        int col = warpN * 64 + nt * 8 + 2 * tig;
        alv[nt][0] = __ldg(&attn_l[col]);
        alv[nt][1] = __ldg(&attn_l[col + 1]);
        arv[nt][0] = __ldg(&attn_r[col]);
        arv[nt][1] = __ldg(&attn_r[col + 1]);
    }

#pragma unroll
    for (int mt = 0; mt < 2; mt++) {
        int row0 = rowBase + warpM * 32 + mt * 16 + grp;
#pragma unroll
        for (int half = 0; half < 2; half++) {   // row0 (c0,c1) / row0+8 (c2,c3)
            float pl[2] = {0.f, 0.f}, pr[2] = {0.f, 0.f};
#pragma unroll
            for (int nt = 0; nt < 8; nt++) {
                int hl = nt >> 2;  // local head (0: cols 0-31, 1: cols 32-63 of warp)
                float c0 = C[mt][nt][half * 2 + 0];
                float c1 = C[mt][nt][half * 2 + 1];
                pl[hl] = fmaf(c0, alv[nt][0], fmaf(c1, alv[nt][1], pl[hl]));
                pr[hl] = fmaf(c0, arv[nt][0], fmaf(c1, arv[nt][1], pr[hl]));
            }
#pragma unroll
            for (int hl = 0; hl < 2; hl++) {
                pl[hl] += __shfl_xor_sync(0xFFFFFFFFu, pl[hl], 1);
                pl[hl] += __shfl_xor_sync(0xFFFFFFFFu, pl[hl], 2);
                pr[hl] += __shfl_xor_sync(0xFFFFFFFFu, pr[hl], 1);
                pr[hl] += __shfl_xor_sync(0xFFFFFFFFu, pr[hl], 2);
            }
            int row = row0 + half * 8;
            if (tig == 0 && row < N) {
                int h0 = warpN * 2;
                g_el[row * 4 + h0 + 0] = pl[0];
                g_el[row * 4 + h0 + 1] = pl[1];
                g_er[row * 4 + h0 + 0] = pr[0];
                g_er[row * 4 + h0 + 1] = pr[1];
            }
        }
    }
}

// ---------------------------------------------------------------------------
// Scan A: per-1024-block exclusive scan of g_cnt -> g_off, totals -> g_bsum
// ---------------------------------------------------------------------------
__global__ void scanA_kernel(int N) {
    __shared__ int wtot[8];
    __shared__ int wexcl[8];
    int tid = threadIdx.x;
    int lane = tid & 31;
    int base = blockIdx.x * 1024 + tid * 4;

    int4 c = make_int4(0, 0, 0, 0);
    if (base + 3 < N) {
        c = *(const int4*)(g_cnt + base);
    } else {
        if (base + 0 < N) c.x = g_cnt[base + 0];
        if (base + 1 < N) c.y = g_cnt[base + 1];
        if (base + 2 < N) c.z = g_cnt[base + 2];
        if (base + 3 < N) c.w = g_cnt[base + 3];
    }
    int tsum = c.x + c.y + c.z + c.w;
    int incl = tsum;
#pragma unroll
    for (int s = 1; s < 32; s <<= 1) {
        int v = __shfl_up_sync(0xFFFFFFFFu, incl, s);
        if (lane >= s) incl += v;
    }
    if (lane == 31) wtot[tid >> 5] = incl;
    __syncthreads();
    if (tid == 0) {
        int r = 0;
#pragma unroll
        for (int w = 0; w < 8; w++) { wexcl[w] = r; r += wtot[w]; }
        g_bsum[blockIdx.x] = r;
    }
    __syncthreads();
    int p = wexcl[tid >> 5] + incl - tsum;
    if (base + 0 < N) g_off[base + 0] = p;
    if (base + 1 < N) g_off[base + 1] = p + c.x;
    if (base + 2 < N) g_off[base + 2] = p + c.x + c.y;
    if (base + 3 < N) g_off[base + 3] = p + c.x + c.y + c.z;
}

// ---------------------------------------------------------------------------
// Scan B: exclusive scan of block totals (single block, 128 threads)
// ---------------------------------------------------------------------------
__global__ void scanB_kernel(int nb) {
    __shared__ int wtot[4];
    __shared__ int wexcl[4];
    int t = threadIdx.x;
    int lane = t & 31;
    int v = (t < nb) ? g_bsum[t] : 0;
    int incl = v;
#pragma unroll
    for (int s = 1; s < 32; s <<= 1) {
        int u = __shfl_up_sync(0xFFFFFFFFu, incl, s);
        if (lane >= s) incl += u;
    }
    if (lane == 31) wtot[t >> 5] = incl;
    __syncthreads();
    if (t == 0) {
        int r = 0;
#pragma unroll
        for (int w = 0; w < 4; w++) { wexcl[w] = r; r += wtot[w]; }
    }
    __syncthreads();
    if (t < nb) g_boff[t] = wexcl[t >> 5] + incl - v;
}

// ---------------------------------------------------------------------------
// Kernel: permute src ids into dst-sorted order
// ---------------------------------------------------------------------------
__global__ void edge_scatter_kernel(const int* __restrict__ src,
                                    const int* __restrict__ dst,
                                    int E) {
    int e = blockIdx.x * blockDim.x + threadIdx.x;
    if (e >= E) return;
    int s = src[e];
    int d = dst[e];
    int r = atomicAdd(&g_cur[d], 1);
    int pos = __ldg(&g_off[d]) + __ldg(&g_boff[d >> 10]) + r;
    g_srcs[pos] = s;
}

// ---------------------------------------------------------------------------
// Kernel: gather aggregation. One warp per dst node. Computes logits, exp,
// softmax, weighted feature sum, bias + ELU; streaming store of output.
// ---------------------------------------------------------------------------
__global__ void __launch_bounds__(256)
aggregate_kernel(const float* __restrict__ bias,
                 float* __restrict__ out,
                 int N) {
    int node = (blockIdx.x * blockDim.x + threadIdx.x) >> 5;
    int lane = threadIdx.x & 31;
    if (node >= N) return;

    int off = g_off[node] + g_boff[node >> 10];
    int cnt = g_cnt[node];
    int h = lane >> 3;

    float er_h = g_er[node * 4 + h];

    float4 acc = make_float4(0.f, 0.f, 0.f, 0.f);
    float den = 0.f;

    const float4* feat4 = (const float4*)g_feat;

    int i = 0;
    for (; i + 4 <= cnt; i += 4) {
        int s0 = g_srcs[off + i + 0];
        int s1 = g_srcs[off + i + 1];
        int s2 = g_srcs[off + i + 2];
        int s3 = g_srcs[off + i + 3];
        float e0 = __ldg(&g_el[s0 * 4 + h]) + er_h;
        float e1 = __ldg(&g_el[s1 * 4 + h]) + er_h;
        float e2 = __ldg(&g_el[s2 * 4 + h]) + er_h;
        float e3 = __ldg(&g_el[s3 * 4 + h]) + er_h;
        float4 f0 = feat4[(size_t)s0 * 32 + lane];
        float4 f1 = feat4[(size_t)s1 * 32 + lane];
        float4 f2 = feat4[(size_t)s2 * 32 + lane];
        float4 f3 = feat4[(size_t)s3 * 32 + lane];
        e0 = e0 > 0.f ? e0 : NEG_SLOPE * e0;
        e1 = e1 > 0.f ? e1 : NEG_SLOPE * e1;
        e2 = e2 > 0.f ? e2 : NEG_SLOPE * e2;
        e3 = e3 > 0.f ? e3 : NEG_SLOPE * e3;
        float w0 = __expf(e0), w1 = __expf(e1), w2 = __expf(e2), w3 = __expf(e3);
        den += (w0 + w1) + (w2 + w3);
        acc.x = fmaf(w0, f0.x, acc.x); acc.y = fmaf(w0, f0.y, acc.y);
        acc.z = fmaf(w0, f0.z, acc.z); acc.w = fmaf(w0, f0.w, acc.w);
        acc.x = fmaf(w1, f1.x, acc.x); acc.y = fmaf(w1, f1.y, acc.y);
        acc.z = fmaf(w1, f1.z, acc.z); acc.w = fmaf(w1, f1.w, acc.w);
        acc.x = fmaf(w2, f2.x, acc.x); acc.y = fmaf(w2, f2.y, acc.y);
        acc.z = fmaf(w2, f2.z, acc.z); acc.w = fmaf(w2, f2.w, acc.w);
        acc.x = fmaf(w3, f3.x, acc.x); acc.y = fmaf(w3, f3.y, acc.y);
        acc.z = fmaf(w3, f3.z, acc.z); acc.w = fmaf(w3, f3.w, acc.w);
    }
    for (; i < cnt; i++) {
        int s0 = g_srcs[off + i];
        float e0 = __ldg(&g_el[s0 * 4 + h]) + er_h;
        e0 = e0 > 0.f ? e0 : NEG_SLOPE * e0;
        float w0 = __expf(e0);
        float4 f0 = feat4[(size_t)s0 * 32 + lane];
        den += w0;
        acc.x = fmaf(w0, f0.x, acc.x); acc.y = fmaf(w0, f0.y, acc.y);
        acc.z = fmaf(w0, f0.z, acc.z); acc.w = fmaf(w0, f0.w, acc.w);
    }

    float inv = __fdividef(1.0f, fmaxf(den, 1e-9f));
    float4 bvec = ((const float4*)bias)[lane];
    acc.x = acc.x * inv + bvec.x;
    acc.y = acc.y * inv + bvec.y;
    acc.z = acc.z * inv + bvec.z;
    acc.w = acc.w * inv + bvec.w;
    acc.x = acc.x > 0.f ? acc.x : expm1f(acc.x);
    acc.y = acc.y > 0.f ? acc.y : expm1f(acc.y);
    acc.z = acc.z > 0.f ? acc.z : expm1f(acc.z);
    acc.w = acc.w > 0.f ? acc.w : expm1f(acc.w);
    __stcs(&((float4*)out)[(size_t)node * 32 + lane], acc);
}

// ---------------------------------------------------------------------------
// Launcher — sort chain forked onto a side stream, overlapping the GEMM.
// Stream/event handles created once and reused across invocations.
// ---------------------------------------------------------------------------
extern "C" void kernel_launch(void* const* d_in, const int* in_sizes, int n_in,
                              void* d_out, int out_size) {
    const float* features = (const float*)d_in[0];
    const int*   src      = (const int*)d_in[1];
    const int*   dst      = (const int*)d_in[2];
    const float* W        = (const float*)d_in[3];
    const float* attn_l   = (const float*)d_in[4];
    const float* attn_r   = (const float*)d_in[5];
    const float* bias     = (const float*)d_in[6];
    float*       out      = (float*)d_out;

    int N = in_sizes[0] / 128;   // 100000
    int E = in_sizes[1];         // 1600000
    int nb = (N + 1023) / 1024;  // scan blocks

    static cudaStream_t s2 = nullptr;
    static cudaEvent_t evFork = nullptr, evJoin = nullptr;
    if (!s2) {
        cudaStreamCreateWithFlags(&s2, cudaStreamNonBlocking);
        cudaEventCreateWithFlags(&evFork, cudaEventDisableTiming);
        cudaEventCreateWithFlags(&evJoin, cudaEventDisableTiming);
        int smem = (128 * AS_STRIDE + 128 * WS_STRIDE) * 4;
        cudaFuncSetAttribute(gemm_kernel, cudaFuncAttributeMaxDynamicSharedMemorySize, smem);
    }

    // fork side stream from the (capture) default stream
    cudaEventRecord(evFork, 0);
    cudaStreamWaitEvent(s2, evFork, 0);

    // side stream: counting-sort chain (independent of GEMM)
    zero_kernel<<<(N + 255) / 256, 256, 0, s2>>>(N);
    hist_kernel<<<(E / 2 + 255) / 256, 256, 0, s2>>>(dst, E);
    scanA_kernel<<<nb, 256, 0, s2>>>(N);
    scanB_kernel<<<1, 128, 0, s2>>>(nb);
    edge_scatter_kernel<<<(E + 255) / 256, 256, 0, s2>>>(src, dst, E);
    cudaEventRecord(evJoin, s2);

    // default stream: tensor-core GEMM with fused el/er epilogue
    int smem = (128 * AS_STRIDE + 128 * WS_STRIDE) * 4;
    gemm_kernel<<<(N + 127) / 128, 256, smem>>>(features, W, attn_l, attn_r, N);

    // join, then aggregate
    cudaStreamWaitEvent(0, evJoin, 0);
    aggregate_kernel<<<(N + 7) / 8, 256>>>(bias, out, N);
}